// round 8
// baseline (speedup 1.0000x reference)
#include <cuda_runtime.h>
#include <cuda_fp16.h>

#define DD 64
#define NU 50000
#define NB 20000
#define NI 40000
// Unified row namespace: g0 (U+I) | g1 (U+B) | g2 (U+B) | agg (B)
#define R1 90000
#define R2 160000
#define R3 230000
#define NROWS 250000
#define NPROWS 230000
#define X16Q (NPROWS * 16)
#define EMAX 5200000
#define NBLK 62
#define NZ4 62500
#define T 256

// ---- device scratch (no allocation; zero-initialized at load) ----
__device__ __half g_x16 [(size_t)NPROWS * DD];
__device__ __half g_f116[(size_t)NPROWS * DD];
__device__ __half g_ili [(size_t)NI * DD];
__device__ float  g_acc [(size_t)NPROWS * DD];
__device__ int    g_ecol[EMAX];
__device__ int    g_lo  [EMAX];
__device__ int    g_cnt [NROWS];
__device__ int    g_rowptr[NROWS + 1];
__device__ unsigned long long g_bstate[NBLK];

static inline unsigned gdiv(long long a, int b) { return (unsigned)((a + b - 1) / b); }

// ---------------- histogram ----------------
__global__ void k_hist(const int* __restrict__ r0, const int* __restrict__ r1p,
                       const int* __restrict__ r2p, const int* __restrict__ r3p,
                       int o1, int o2, int o3, int etot) {
    int t = blockIdx.x * blockDim.x + threadIdx.x;
    if (t >= etot) return;
    const int* rp; int e, ro;
    if (t < o1)      { rp = r0;  e = t;      ro = 0;  }
    else if (t < o2) { rp = r1p; e = t - o1; ro = R1; }
    else if (t < o3) { rp = r2p; e = t - o2; ro = R2; }
    else             { rp = r3p; e = t - o3; ro = R3; }
    int grow = __ldg(rp + e) + ro;
    int slot = atomicAdd(&g_cnt[grow], 1);
    g_lo[t] = (grow << 8) | slot;
}

// ---------------- single-pass decoupled-lookback exclusive scan ----------------
__global__ void __launch_bounds__(1024) k_scan() {
    __shared__ int wsum[32];
    __shared__ int s_prefix, s_agg;
    int tid = threadIdx.x, lane = tid & 31, wid = tid >> 5;
    int bid = blockIdx.x;
    int i0 = bid * 4096 + tid * 4;
    int v[4];
    #pragma unroll
    for (int j = 0; j < 4; j++) v[j] = (i0 + j < NROWS) ? g_cnt[i0 + j] : 0;
    int tsum = v[0] + v[1] + v[2] + v[3];
    int sc = tsum;
    #pragma unroll
    for (int o = 1; o < 32; o <<= 1) {
        int u = __shfl_up_sync(0xffffffffu, sc, o);
        if (lane >= o) sc += u;
    }
    if (lane == 31) wsum[wid] = sc;
    __syncthreads();
    if (wid == 0) {
        int ws = wsum[lane];
        int sw = ws;
        #pragma unroll
        for (int o = 1; o < 32; o <<= 1) {
            int u = __shfl_up_sync(0xffffffffu, sw, o);
            if (lane >= o) sw += u;
        }
        wsum[lane] = sw - ws;
        int agg = __shfl_sync(0xffffffffu, sw, 31);
        if (lane == 0) s_agg = agg;
        if (lane == 0)
            atomicExch(&g_bstate[bid],
                       (bid == 0 ? (2ULL << 32) : (1ULL << 32)) | (unsigned)agg);
        int prefix = 0;
        if (bid > 0) {
            int j = bid - 1;
            for (;;) {
                int idx = j - lane;
                unsigned long long s = (idx >= 0) ? atomicAdd(&g_bstate[idx], 0ULL)
                                                  : (2ULL << 32);
                unsigned flag = (unsigned)(s >> 32);
                unsigned invb = __ballot_sync(0xffffffffu, flag == 0u);
                unsigned preb = __ballot_sync(0xffffffffu, flag == 2u);
                int p  = preb ? (__ffs(preb) - 1) : 32;
                int iv = invb ? (__ffs(invb) - 1) : 32;
                if (iv < p) continue;
                int cnt = (p < 32) ? (p + 1) : 32;
                int val = (lane < cnt) ? (int)(s & 0xffffffffu) : 0;
                #pragma unroll
                for (int o = 16; o; o >>= 1) val += __shfl_xor_sync(0xffffffffu, val, o);
                prefix += val;
                if (p < 32) break;
                j -= 32;
            }
            if (lane == 0)
                atomicExch(&g_bstate[bid], (2ULL << 32) | (unsigned)(prefix + agg));
        }
        if (lane == 0) s_prefix = prefix;
    }
    __syncthreads();
    int excl = s_prefix + wsum[wid] + (sc - tsum);
    #pragma unroll
    for (int j = 0; j < 4; j++) {
        if (i0 + j < NROWS) g_rowptr[i0 + j] = excl;
        excl += v[j];
    }
    if (bid == NBLK - 1 && tid == 0) g_rowptr[NROWS] = s_prefix + s_agg;
}

__device__ __forceinline__ float nf_of(int grow) {
    int d = __ldg(g_rowptr + grow + 1) - __ldg(g_rowptr + grow);
    return 1.f / (sqrtf((float)d) + 1e-8f);
}

// ---------------- fused mid: scatter + scaled fp16 prep + state re-zero ----------------
__global__ void k_mid(const int* __restrict__ r0, const int* __restrict__ r1p,
                      const int* __restrict__ r2p, const int* __restrict__ r3p,
                      const float4* __restrict__ u, const float4* __restrict__ b,
                      const float4* __restrict__ itm,
                      int n0, int n1, int n2, int n3,
                      int o1, int o2, int o3, int etot) {
    int t = blockIdx.x * blockDim.x + threadIdx.x;
    if (t < etot) {
        const int* cp; int e, ro;
        if (t < o1)      { cp = r0  + n0; e = t;      ro = 0;  }
        else if (t < o2) { cp = r1p + n1; e = t - o1; ro = R1; }
        else if (t < o3) { cp = r2p + n2; e = t - o2; ro = R2; }
        else             { cp = r3p + n3; e = t - o3; ro = 0;  }
        int packed = g_lo[t];
        int pos = __ldg(g_rowptr + (packed >> 8)) + (packed & 255);
        g_ecol[pos] = __ldg(cp + e) + ro;
    } else if (t < etot + X16Q) {
        int q = t - etot;
        int grow = q >> 4, sub = q & 15;
        float nf = nf_of(grow);
        int ro = (grow < R1) ? 0 : ((grow < R2) ? R1 : R2);
        int lrow = grow - ro;
        const float4* xp;
        if (lrow < NU)       xp = u + (size_t)lrow * 16;
        else if (grow < R1)  xp = itm + (size_t)(lrow - NU) * 16;
        else                 xp = b + (size_t)(lrow - NU) * 16;
        float4 v = __ldg(xp + sub);
        __half2 h0 = __float22half2_rn(make_float2(v.x * nf, v.y * nf));
        __half2 h1 = __float22half2_rn(make_float2(v.z * nf, v.w * nf));
        ((uint2*)g_x16)[q] = make_uint2(*(unsigned*)&h0, *(unsigned*)&h1);
    } else {
        int z = t - etot - X16Q;
        if (z < NZ4) ((int4*)g_cnt)[z] = make_int4(0, 0, 0, 0);
        else if (z < NZ4 + NBLK) g_bstate[z - NZ4] = 0ULL;
    }
}

// ---------------- warp-per-row gather: 32 lanes, LDG.32 per edge (1 wf) ----------------
__device__ __forceinline__ __half2 h2of(unsigned x) { return *reinterpret_cast<__half2*>(&x); }

__device__ __forceinline__ void facc(float2& s, __half2 h) {
    float2 f = __half22float2(h);
    s.x += f.x; s.y += f.y;
}

__device__ __forceinline__ void gatherw(const unsigned* __restrict__ src,
                                        int beg, int end, int lane, float2& s) {
    s = make_float2(0.f, 0.f);
    int i = beg;
    int head = (4 - (beg & 3)) & 3;
    if (head > end - beg) head = end - beg;
    for (int k = 0; k < head; k++, i++) {
        unsigned x = __ldg(src + (size_t)__ldg(g_ecol + i) * 32 + lane);
        facc(s, h2of(x));
    }
    for (; i + 8 <= end; i += 8) {
        int4 ca = __ldg((const int4*)(g_ecol + i));
        int4 cb = __ldg((const int4*)(g_ecol + i + 4));
        unsigned x0 = __ldg(src + (size_t)ca.x * 32 + lane);
        unsigned x1 = __ldg(src + (size_t)ca.y * 32 + lane);
        unsigned x2 = __ldg(src + (size_t)ca.z * 32 + lane);
        unsigned x3 = __ldg(src + (size_t)ca.w * 32 + lane);
        unsigned x4 = __ldg(src + (size_t)cb.x * 32 + lane);
        unsigned x5 = __ldg(src + (size_t)cb.y * 32 + lane);
        unsigned x6 = __ldg(src + (size_t)cb.z * 32 + lane);
        unsigned x7 = __ldg(src + (size_t)cb.w * 32 + lane);
        facc(s, __hadd2(h2of(x0), h2of(x1)));
        facc(s, __hadd2(h2of(x2), h2of(x3)));
        facc(s, __hadd2(h2of(x4), h2of(x5)));
        facc(s, __hadd2(h2of(x6), h2of(x7)));
    }
    if (i + 4 <= end) {
        int4 ca = __ldg((const int4*)(g_ecol + i));
        unsigned x0 = __ldg(src + (size_t)ca.x * 32 + lane);
        unsigned x1 = __ldg(src + (size_t)ca.y * 32 + lane);
        unsigned x2 = __ldg(src + (size_t)ca.z * 32 + lane);
        unsigned x3 = __ldg(src + (size_t)ca.w * 32 + lane);
        facc(s, __hadd2(h2of(x0), h2of(x1)));
        facc(s, __hadd2(h2of(x2), h2of(x3)));
        i += 4;
    }
    for (; i < end; i++) {
        unsigned x = __ldg(src + (size_t)__ldg(g_ecol + i) * 32 + lane);
        facc(s, h2of(x));
    }
}

__device__ __forceinline__ float norm_inv32(float2 s) {
    float ss = s.x * s.x + s.y * s.y;
    #pragma unroll
    for (int o = 16; o; o >>= 1) ss += __shfl_xor_sync(0xffffffffu, ss, o);
    return 1.f / fmaxf(sqrtf(ss), 1e-12f);
}

// Layer 1: raw = gather(x16); f116 = raw*16*nf^2; acc = x0 + normalize(raw)
__global__ void k_l1(const float* __restrict__ users, const float* __restrict__ bundles,
                     const float* __restrict__ items) {
    int t = blockIdx.x * blockDim.x + threadIdx.x;
    int row = t >> 5, lane = t & 31;
    if (row >= NPROWS) return;
    int beg = __ldg(g_rowptr + row), end = __ldg(g_rowptr + row + 1);
    float2 s;
    gatherw((const unsigned*)g_x16, beg, end, lane, s);
    float nf = 1.f / (sqrtf((float)(end - beg)) + 1e-8f);
    float fs = 16.f * nf * nf;
    float inv = norm_inv32(s);
    __half2 h = __float22half2_rn(make_float2(s.x * fs, s.y * fs));
    ((unsigned*)g_f116)[(size_t)row * 32 + lane] = *(unsigned*)&h;
    int ro = (row < R1) ? 0 : ((row < R2) ? R1 : R2);
    int lrow = row - ro;
    const float2* xp;
    if (lrow < NU)      xp = (const float2*)users + (size_t)lrow * 32;
    else if (row < R1)  xp = (const float2*)items + (size_t)(lrow - NU) * 32;
    else                xp = (const float2*)bundles + (size_t)(lrow - NU) * 32;
    float2 a = __ldg(xp + lane);
    a.x += s.x * inv; a.y += s.y * inv;
    ((float2*)g_acc)[(size_t)row * 32 + lane] = a;
}

// Layer 2: raw2 = gather(f116); result = acc + normalize(raw2)
__global__ void k_l2(float* __restrict__ out) {
    int t = blockIdx.x * blockDim.x + threadIdx.x;
    int row = t >> 5, lane = t & 31;
    if (row >= NPROWS) return;
    int beg = __ldg(g_rowptr + row), end = __ldg(g_rowptr + row + 1);
    float2 s;
    gatherw((const unsigned*)g_f116, beg, end, lane, s);
    float inv = norm_inv32(s);
    float2 a = ((const float2*)g_acc)[(size_t)row * 32 + lane];
    a.x += s.x * inv; a.y += s.y * inv;
    if (row >= NU && row < R1) {
        __half2 h = __float22half2_rn(make_float2(a.x, a.y));
        ((unsigned*)g_ili)[(size_t)(row - NU) * 32 + lane] = *(unsigned*)&h;
        return;
    }
    float2* d;
    if (row < NU)            d = (float2*)out + (size_t)row * 32;
    else if (row < R1 + NU)  d = (float2*)out + ((size_t)NU + (row - R1)) * 32;
    else if (row < R2)       d = (float2*)out + ((size_t)3 * NU + NB + (row - R1 - NU)) * 32;
    else if (row < R2 + NU)  d = (float2*)out + ((size_t)2 * NU + (row - R2)) * 32;
    else                     d = (float2*)out + ((size_t)3 * NU + 2 * NB + (row - R2 - NU)) * 32;
    d[lane] = a;
}

// Bundle aggregation: out[3U+b] = (1/max(deg,1)) * sum IL_i
__global__ void k_agg(float* __restrict__ out) {
    int t = blockIdx.x * blockDim.x + threadIdx.x;
    int row = t >> 5, lane = t & 31;
    if (row >= NB) return;
    int grow = R3 + row;
    int beg = __ldg(g_rowptr + grow), end = __ldg(g_rowptr + grow + 1);
    float2 s;
    gatherw((const unsigned*)g_ili, beg, end, lane, s);
    float fac = 1.f / fmaxf((float)(end - beg), 1.f);
    s.x *= fac; s.y *= fac;
    ((float2*)out)[((size_t)3 * NU + row) * 32 + lane] = s;
}

extern "C" void kernel_launch(void* const* d_in, const int* in_sizes, int n_in,
                              void* d_out, int out_size) {
    const float* users   = (const float*)d_in[0];
    const float* bundles = (const float*)d_in[1];
    const float* items   = (const float*)d_in[2];
    const int*   ui_idx  = (const int*)d_in[3];
    const int*   ub_idx  = (const int*)d_in[5];
    const int*   ubx_idx = (const int*)d_in[7];
    const int*   agg_idx = (const int*)d_in[9];
    int n0 = in_sizes[4], n1 = in_sizes[6], n2 = in_sizes[8], n3 = in_sizes[10];
    int o1 = n0, o2 = o1 + n1, o3 = o2 + n2, etot = o3 + n3;
    float* out = (float*)d_out;

    k_hist<<<gdiv(etot, T), T>>>(ui_idx, ub_idx, ubx_idx, agg_idx, o1, o2, o3, etot);
    k_scan<<<NBLK, 1024>>>();
    long long midN = (long long)etot + X16Q + NZ4 + NBLK;
    k_mid<<<gdiv(midN, T), T>>>(ui_idx, ub_idx, ubx_idx, agg_idx,
                                (const float4*)users, (const float4*)bundles,
                                (const float4*)items,
                                n0, n1, n2, n3, o1, o2, o3, etot);
    k_l1<<<gdiv((long long)NPROWS * 32, T), T>>>(users, bundles, items);
    k_l2<<<gdiv((long long)NPROWS * 32, T), T>>>(out);
    k_agg<<<gdiv((long long)NB * 32, T), T>>>(out);
}

// round 9
// speedup vs baseline: 1.3300x; 1.3300x over previous
#include <cuda_runtime.h>
#include <cuda_fp16.h>

#define DD 64
#define NU 50000
#define NB 20000
#define NI 40000
// Unified row namespace: g0 (U+I) | g1 (U+B) | g2 (U+B) | agg (B)
#define R1 90000
#define R2 160000
#define R3 230000
#define NROWS 250000
#define NPROWS 230000
#define X16Q (NPROWS * 16)
#define EMAX 5200000
#define NBLK 62
#define NZ4 62500
#define T 256

// ---- device scratch (no allocation; zero-initialized at load) ----
__device__ __half g_x16  [(size_t)NPROWS * DD];  // x0 * nf (fp16)
__device__ __half g_f116 [(size_t)NPROWS * DD];  // layer-1 sources (fp16, col-scaled)
__device__ __half g_ili  [(size_t)NI * DD];      // IL_i for aggregation
__device__ __half g_acc16[(size_t)NPROWS * DD];  // fp16 accumulator
__device__ int    g_ecol[EMAX];
__device__ int    g_lo  [EMAX];
__device__ int    g_cnt [NROWS];
__device__ int    g_rowptr[NROWS + 1];
__device__ unsigned long long g_bstate[NBLK];

static inline unsigned gdiv(long long a, int b) { return (unsigned)((a + b - 1) / b); }

// ---------------- histogram ----------------
__global__ void k_hist(const int* __restrict__ r0, const int* __restrict__ r1p,
                       const int* __restrict__ r2p, const int* __restrict__ r3p,
                       int o1, int o2, int o3, int etot) {
    int t = blockIdx.x * blockDim.x + threadIdx.x;
    if (t >= etot) return;
    const int* rp; int e, ro;
    if (t < o1)      { rp = r0;  e = t;      ro = 0;  }
    else if (t < o2) { rp = r1p; e = t - o1; ro = R1; }
    else if (t < o3) { rp = r2p; e = t - o2; ro = R2; }
    else             { rp = r3p; e = t - o3; ro = R3; }
    int grow = __ldg(rp + e) + ro;
    int slot = atomicAdd(&g_cnt[grow], 1);
    g_lo[t] = (grow << 8) | slot;
}

// ---------------- single-pass decoupled-lookback exclusive scan ----------------
__global__ void __launch_bounds__(1024) k_scan() {
    __shared__ int wsum[32];
    __shared__ int s_prefix, s_agg;
    int tid = threadIdx.x, lane = tid & 31, wid = tid >> 5;
    int bid = blockIdx.x;
    int i0 = bid * 4096 + tid * 4;
    int v[4];
    #pragma unroll
    for (int j = 0; j < 4; j++) v[j] = (i0 + j < NROWS) ? g_cnt[i0 + j] : 0;
    int tsum = v[0] + v[1] + v[2] + v[3];
    int sc = tsum;
    #pragma unroll
    for (int o = 1; o < 32; o <<= 1) {
        int u = __shfl_up_sync(0xffffffffu, sc, o);
        if (lane >= o) sc += u;
    }
    if (lane == 31) wsum[wid] = sc;
    __syncthreads();
    if (wid == 0) {
        int ws = wsum[lane];
        int sw = ws;
        #pragma unroll
        for (int o = 1; o < 32; o <<= 1) {
            int u = __shfl_up_sync(0xffffffffu, sw, o);
            if (lane >= o) sw += u;
        }
        wsum[lane] = sw - ws;
        int agg = __shfl_sync(0xffffffffu, sw, 31);
        if (lane == 0) s_agg = agg;
        if (lane == 0)
            atomicExch(&g_bstate[bid],
                       (bid == 0 ? (2ULL << 32) : (1ULL << 32)) | (unsigned)agg);
        int prefix = 0;
        if (bid > 0) {
            int j = bid - 1;
            for (;;) {
                int idx = j - lane;
                unsigned long long s = (idx >= 0) ? atomicAdd(&g_bstate[idx], 0ULL)
                                                  : (2ULL << 32);
                unsigned flag = (unsigned)(s >> 32);
                unsigned invb = __ballot_sync(0xffffffffu, flag == 0u);
                unsigned preb = __ballot_sync(0xffffffffu, flag == 2u);
                int p  = preb ? (__ffs(preb) - 1) : 32;
                int iv = invb ? (__ffs(invb) - 1) : 32;
                if (iv < p) continue;
                int cnt = (p < 32) ? (p + 1) : 32;
                int val = (lane < cnt) ? (int)(s & 0xffffffffu) : 0;
                #pragma unroll
                for (int o = 16; o; o >>= 1) val += __shfl_xor_sync(0xffffffffu, val, o);
                prefix += val;
                if (p < 32) break;
                j -= 32;
            }
            if (lane == 0)
                atomicExch(&g_bstate[bid], (2ULL << 32) | (unsigned)(prefix + agg));
        }
        if (lane == 0) s_prefix = prefix;
    }
    __syncthreads();
    int excl = s_prefix + wsum[wid] + (sc - tsum);
    #pragma unroll
    for (int j = 0; j < 4; j++) {
        if (i0 + j < NROWS) g_rowptr[i0 + j] = excl;
        excl += v[j];
    }
    if (bid == NBLK - 1 && tid == 0) g_rowptr[NROWS] = s_prefix + s_agg;
}

// ---------------- fused mid: scatter + scaled fp16 prep + state re-zero ----------------
__global__ void k_mid(const int* __restrict__ r0, const int* __restrict__ r1p,
                      const int* __restrict__ r2p, const int* __restrict__ r3p,
                      const float4* __restrict__ u, const float4* __restrict__ b,
                      const float4* __restrict__ itm,
                      int n0, int n1, int n2, int n3,
                      int o1, int o2, int o3, int etot) {
    int t = blockIdx.x * blockDim.x + threadIdx.x;
    if (t < etot) {
        const int* cp; int e, ro;
        if (t < o1)      { cp = r0  + n0; e = t;      ro = 0;  }
        else if (t < o2) { cp = r1p + n1; e = t - o1; ro = R1; }
        else if (t < o3) { cp = r2p + n2; e = t - o2; ro = R2; }
        else             { cp = r3p + n3; e = t - o3; ro = 0;  }
        int packed = g_lo[t];
        int pos = __ldg(g_rowptr + (packed >> 8)) + (packed & 255);
        g_ecol[pos] = __ldg(cp + e) + ro;
    } else if (t < etot + X16Q) {
        int q = t - etot;
        int grow = q >> 4, sub = q & 15;
        int d = __ldg(g_rowptr + grow + 1) - __ldg(g_rowptr + grow);
        float nf = (d > 0) ? 1.f / (sqrtf((float)d) + 1e-8f) : 1.f;  // deg-0: identity
        int ro = (grow < R1) ? 0 : ((grow < R2) ? R1 : R2);
        int lrow = grow - ro;
        const float4* xp;
        if (lrow < NU)       xp = u + (size_t)lrow * 16;
        else if (grow < R1)  xp = itm + (size_t)(lrow - NU) * 16;
        else                 xp = b + (size_t)(lrow - NU) * 16;
        float4 v = __ldg(xp + sub);
        __half2 h0 = __float22half2_rn(make_float2(v.x * nf, v.y * nf));
        __half2 h1 = __float22half2_rn(make_float2(v.z * nf, v.w * nf));
        ((uint2*)g_x16)[q] = make_uint2(*(unsigned*)&h0, *(unsigned*)&h1);
    } else {
        int z = t - etot - X16Q;
        if (z < NZ4) ((int4*)g_cnt)[z] = make_int4(0, 0, 0, 0);
        else if (z < NZ4 + NBLK) g_bstate[z - NZ4] = 0ULL;
    }
}

// ---------------- gathers: 8 lanes/row, 16B fp16 loads, unroll 4 ----------------
__device__ __forceinline__ void hadd8(float4& a, float4& b, uint4 raw) {
    __half2* h = (__half2*)&raw;
    float2 f0 = __half22float2(h[0]), f1 = __half22float2(h[1]);
    float2 f2 = __half22float2(h[2]), f3 = __half22float2(h[3]);
    a.x += f0.x; a.y += f0.y; a.z += f1.x; a.w += f1.y;
    b.x += f2.x; b.y += f2.y; b.z += f3.x; b.w += f3.y;
}

__device__ __forceinline__ void cvt8(float4& a, float4& b, uint4 raw) {
    __half2* h = (__half2*)&raw;
    float2 f0 = __half22float2(h[0]), f1 = __half22float2(h[1]);
    float2 f2 = __half22float2(h[2]), f3 = __half22float2(h[3]);
    a = make_float4(f0.x, f0.y, f1.x, f1.y);
    b = make_float4(f2.x, f2.y, f3.x, f3.y);
}

__device__ __forceinline__ uint4 pack8(float4 a, float4 b) {
    __half2 h0 = __float22half2_rn(make_float2(a.x, a.y));
    __half2 h1 = __float22half2_rn(make_float2(a.z, a.w));
    __half2 h2 = __float22half2_rn(make_float2(b.x, b.y));
    __half2 h3 = __float22half2_rn(make_float2(b.z, b.w));
    return make_uint4(*(unsigned*)&h0, *(unsigned*)&h1, *(unsigned*)&h2, *(unsigned*)&h3);
}

__device__ __forceinline__ void gather8(const uint4* __restrict__ src, int beg, int end,
                                        int lane, float4& sa, float4& sb) {
    sa = make_float4(0.f, 0.f, 0.f, 0.f);
    sb = make_float4(0.f, 0.f, 0.f, 0.f);
    int i = beg;
    for (; i + 4 <= end; i += 4) {
        int c0 = __ldg(g_ecol + i),     c1 = __ldg(g_ecol + i + 1);
        int c2 = __ldg(g_ecol + i + 2), c3 = __ldg(g_ecol + i + 3);
        uint4 x0 = __ldg(src + (size_t)c0 * 8 + lane);
        uint4 x1 = __ldg(src + (size_t)c1 * 8 + lane);
        uint4 x2 = __ldg(src + (size_t)c2 * 8 + lane);
        uint4 x3 = __ldg(src + (size_t)c3 * 8 + lane);
        hadd8(sa, sb, x0); hadd8(sa, sb, x1); hadd8(sa, sb, x2); hadd8(sa, sb, x3);
    }
    for (; i < end; i++) {
        uint4 x0 = __ldg(src + (size_t)__ldg(g_ecol + i) * 8 + lane);
        hadd8(sa, sb, x0);
    }
}

__device__ __forceinline__ float norm_inv8(float4 a, float4 b) {
    float ss = a.x * a.x + a.y * a.y + a.z * a.z + a.w * a.w
             + b.x * b.x + b.y * b.y + b.z * b.z + b.w * b.w;
    #pragma unroll
    for (int o = 4; o; o >>= 1) ss += __shfl_xor_sync(0xffffffffu, ss, o, 8);
    return 1.f / fmaxf(sqrtf(ss), 1e-12f);
}

// Layer 1: raw = gather(x16); f116 = raw*16*nf^2; acc16 = x16*rsf + normalize(raw)
__global__ void k_l1() {
    int t = blockIdx.x * blockDim.x + threadIdx.x;
    int row = t >> 3, lane = t & 7;
    if (row >= NPROWS) return;
    int beg = __ldg(g_rowptr + row), end = __ldg(g_rowptr + row + 1);
    float4 sa, sb;
    gather8((const uint4*)g_x16, beg, end, lane, sa, sb);
    int deg = end - beg;
    float nf = (deg > 0) ? 1.f / (sqrtf((float)deg) + 1e-8f) : 1.f;
    float rsf = (deg > 0) ? (sqrtf((float)deg) + 1e-8f) : 1.f;  // exact 1/nf
    float fs = 16.f * nf * nf;
    float inv = norm_inv8(sa, sb);
    ((uint4*)g_f116)[(size_t)row * 8 + lane] =
        pack8(make_float4(sa.x * fs, sa.y * fs, sa.z * fs, sa.w * fs),
              make_float4(sb.x * fs, sb.y * fs, sb.z * fs, sb.w * fs));
    // reconstruct x0 from own x16 row (saves the fp32 feature re-read)
    uint4 xo = __ldg((const uint4*)g_x16 + (size_t)row * 8 + lane);
    float4 a0, a1;
    cvt8(a0, a1, xo);
    a0.x = a0.x * rsf + sa.x * inv; a0.y = a0.y * rsf + sa.y * inv;
    a0.z = a0.z * rsf + sa.z * inv; a0.w = a0.w * rsf + sa.w * inv;
    a1.x = a1.x * rsf + sb.x * inv; a1.y = a1.y * rsf + sb.y * inv;
    a1.z = a1.z * rsf + sb.z * inv; a1.w = a1.w * rsf + sb.w * inv;
    ((uint4*)g_acc16)[(size_t)row * 8 + lane] = pack8(a0, a1);
}

// Layer 2: raw2 = gather(f116); result = acc16 + normalize(raw2)
__global__ void k_l2(float* __restrict__ out) {
    int t = blockIdx.x * blockDim.x + threadIdx.x;
    int row = t >> 3, lane = t & 7;
    if (row >= NPROWS) return;
    int beg = __ldg(g_rowptr + row), end = __ldg(g_rowptr + row + 1);
    float4 sa, sb;
    gather8((const uint4*)g_f116, beg, end, lane, sa, sb);
    float inv = norm_inv8(sa, sb);
    uint4 araw = ((const uint4*)g_acc16)[(size_t)row * 8 + lane];
    float4 a0, a1;
    cvt8(a0, a1, araw);
    a0.x += sa.x * inv; a0.y += sa.y * inv; a0.z += sa.z * inv; a0.w += sa.w * inv;
    a1.x += sb.x * inv; a1.y += sb.y * inv; a1.z += sb.z * inv; a1.w += sb.w * inv;
    if (row >= NU && row < R1) {
        ((uint4*)g_ili)[(size_t)(row - NU) * 8 + lane] = pack8(a0, a1);
        return;
    }
    float4* d;
    if (row < NU)            d = (float4*)out + (size_t)row * 16;
    else if (row < R1 + NU)  d = (float4*)out + ((size_t)NU + (row - R1)) * 16;
    else if (row < R2)       d = (float4*)out + ((size_t)3 * NU + NB + (row - R1 - NU)) * 16;
    else if (row < R2 + NU)  d = (float4*)out + ((size_t)2 * NU + (row - R2)) * 16;
    else                     d = (float4*)out + ((size_t)3 * NU + 2 * NB + (row - R2 - NU)) * 16;
    d[lane * 2]     = a0;
    d[lane * 2 + 1] = a1;
}

// Bundle aggregation: out[3U+b] = (1/max(deg,1)) * sum IL_i
__global__ void k_agg(float* __restrict__ out) {
    int t = blockIdx.x * blockDim.x + threadIdx.x;
    int row = t >> 3, lane = t & 7;
    if (row >= NB) return;
    int grow = R3 + row;
    int beg = __ldg(g_rowptr + grow), end = __ldg(g_rowptr + grow + 1);
    float4 sa, sb;
    gather8((const uint4*)g_ili, beg, end, lane, sa, sb);
    float fac = 1.f / fmaxf((float)(end - beg), 1.f);
    sa.x *= fac; sa.y *= fac; sa.z *= fac; sa.w *= fac;
    sb.x *= fac; sb.y *= fac; sb.z *= fac; sb.w *= fac;
    float4* d = (float4*)out + ((size_t)3 * NU + row) * 16;
    d[lane * 2]     = sa;
    d[lane * 2 + 1] = sb;
}

extern "C" void kernel_launch(void* const* d_in, const int* in_sizes, int n_in,
                              void* d_out, int out_size) {
    const float* users   = (const float*)d_in[0];
    const float* bundles = (const float*)d_in[1];
    const float* items   = (const float*)d_in[2];
    const int*   ui_idx  = (const int*)d_in[3];
    const int*   ub_idx  = (const int*)d_in[5];
    const int*   ubx_idx = (const int*)d_in[7];
    const int*   agg_idx = (const int*)d_in[9];
    int n0 = in_sizes[4], n1 = in_sizes[6], n2 = in_sizes[8], n3 = in_sizes[10];
    int o1 = n0, o2 = o1 + n1, o3 = o2 + n2, etot = o3 + n3;
    float* out = (float*)d_out;

    k_hist<<<gdiv(etot, T), T>>>(ui_idx, ub_idx, ubx_idx, agg_idx, o1, o2, o3, etot);
    k_scan<<<NBLK, 1024>>>();
    long long midN = (long long)etot + X16Q + NZ4 + NBLK;
    k_mid<<<gdiv(midN, T), T>>>(ui_idx, ub_idx, ubx_idx, agg_idx,
                                (const float4*)users, (const float4*)bundles,
                                (const float4*)items,
                                n0, n1, n2, n3, o1, o2, o3, etot);
    k_l1<<<gdiv((long long)NPROWS * 8, T), T>>>();
    k_l2<<<gdiv((long long)NPROWS * 8, T), T>>>(out);
    k_agg<<<gdiv((long long)NB * 8, T), T>>>(out);
}